// round 15
// baseline (speedup 1.0000x reference)
#include <cuda_runtime.h>
#include <math.h>

#define T_TOK 4096   // B*S
#define HDIM  2048
#define NEXP  8
#define DDIM  2048

#define BM 128
#define BN 128
#define BK 16
#define ASTR 20     // BK + 4 pad: conflict-free fragment reads
#define BSTR 136    // BN + 8 pad: stride % 32 == 8 -> conflict-free
#define NSTAGE 4

#define A_STAGE_BYTES (BM * ASTR * 4)                       // 10240
#define B_STAGE_BYTES (BK * BSTR * 4)                       // 8704
#define SMEM_BYTES (NSTAGE * (A_STAGE_BYTES + B_STAGE_BYTES))  // 75776

// ---- scratch (static device globals: no runtime allocation) ----
__device__ int   g_cnt[NEXP];
__device__ int   g_tok[NEXP * T_TOK];    // token*2 + slot
__device__ float g_gate[NEXP * T_TOK];
__device__ float g_c[(size_t)T_TOK * DDIM];          // combined expert out (atomicAdd)
__device__ float g_xr[(size_t)T_TOK * HDIM];         // tf32-rounded x
__device__ float g_ewr[(size_t)NEXP * HDIM * DDIM];  // tf32-rounded expert_w
__device__ float g_owr[(size_t)DDIM * DDIM];         // tf32-rounded out_w

__device__ __forceinline__ float gelu_tanh(float v) {
    float v3 = v * v * v;
    return 0.5f * v * (1.0f + tanhf(0.7978845608028654f * (v + 0.044715f * v3)));
}

// fp32 -> tf32 round-to-nearest (value form, low mantissa bits zeroed)
__device__ __forceinline__ float tf32r(float f) {
    unsigned u;
    asm("cvt.rna.tf32.f32 %0, %1;" : "=r"(u) : "f"(f));
    return __uint_as_float(u);
}

__device__ __forceinline__ void mma_tf32(float* c, const unsigned* a, const unsigned* b) {
    asm volatile(
        "mma.sync.aligned.m16n8k8.row.col.f32.tf32.tf32.f32 "
        "{%0,%1,%2,%3}, {%4,%5,%6,%7}, {%8,%9}, {%0,%1,%2,%3};"
        : "+f"(c[0]), "+f"(c[1]), "+f"(c[2]), "+f"(c[3])
        : "r"(a[0]), "r"(a[1]), "r"(a[2]), "r"(a[3]), "r"(b[0]), "r"(b[1]));
}

__device__ __forceinline__ void cp16(unsigned dst, const void* src, int sz) {
    asm volatile("cp.async.cg.shared.global [%0], [%1], 16, %2;\n"
                 :: "r"(dst), "l"(src), "r"(sz));
}
__device__ __forceinline__ void cp_commit() {
    asm volatile("cp.async.commit_group;\n" ::: "memory");
}
__device__ __forceinline__ void cp_wait2() {
    asm volatile("cp.async.wait_group 2;\n" ::: "memory");
}

// One k-stage (BK=16 = two k8 chunks); 4 warps, each owns a 64x64 tile.
// Halves fragment-LDS bytes per MAC vs the 8x(64x32) layout.
__device__ __forceinline__ void compute_stage(
    const unsigned (*__restrict__ As)[ASTR],
    const unsigned (*__restrict__ Bs)[BSTR],
    float c[4][8][4], int wm, int wn, int lq, int tg)
{
#pragma unroll
    for (int kc = 0; kc < BK; kc += 8) {
        unsigned af[4][4];
        unsigned bf[8][2];
#pragma unroll
        for (int mt = 0; mt < 4; mt++) {
            int r = wm * 64 + mt * 16 + lq;
            af[mt][0] = As[r][kc + tg];
            af[mt][1] = As[r + 8][kc + tg];
            af[mt][2] = As[r][kc + tg + 4];
            af[mt][3] = As[r + 8][kc + tg + 4];
        }
#pragma unroll
        for (int nt = 0; nt < 8; nt++) {
            int nn = wn * 64 + nt * 8 + lq;
            bf[nt][0] = Bs[kc + tg][nn];
            bf[nt][1] = Bs[kc + tg + 4][nn];
        }
#pragma unroll
        for (int mt = 0; mt < 4; mt++)
#pragma unroll
            for (int nt = 0; nt < 8; nt++)
                mma_tf32(c[mt][nt], af[mt], bf[nt]);
    }
}

// Zero g_cnt and g_c (float4 grid-stride)
__global__ void zero_kernel() {
    if (blockIdx.x == 0 && threadIdx.x < NEXP) g_cnt[threadIdx.x] = 0;
    int i = blockIdx.x * blockDim.x + threadIdx.x;
    const int n4 = T_TOK * DDIM / 4;
    float4 z = make_float4(0.f, 0.f, 0.f, 0.f);
    for (; i < n4; i += gridDim.x * blockDim.x)
        ((float4*)g_c)[i] = z;
}

// Pre-round a tensor to tf32 (vectorized, grid-stride)
__global__ void preround_kernel(const float* __restrict__ src,
                                float* __restrict__ dst, int n4) {
    int i = blockIdx.x * blockDim.x + threadIdx.x;
    for (; i < n4; i += gridDim.x * blockDim.x) {
        float4 v = ((const float4*)src)[i];
        v.x = tf32r(v.x); v.y = tf32r(v.y); v.z = tf32r(v.z); v.w = tf32r(v.w);
        ((float4*)dst)[i] = v;
    }
}

// In-place rna-round g_c: one rounding applied AFTER the two-expert sum.
__global__ void round_gc_kernel() {
    int i = blockIdx.x * blockDim.x + threadIdx.x;
    const int n4 = T_TOK * DDIM / 4;
    for (; i < n4; i += gridDim.x * blockDim.x) {
        float4 v = ((const float4*)g_c)[i];
        v.x = tf32r(v.x); v.y = tf32r(v.y); v.z = tf32r(v.z); v.w = tf32r(v.w);
        ((float4*)g_c)[i] = v;
    }
}

// One block per token: logits -> softmax -> top2 -> renorm -> append to lists.
// Also writes g_xr = tf32-rounded x (fused: x is already being read).
__global__ void router_kernel(const float* __restrict__ x,
                              const float* __restrict__ rw,
                              const float* __restrict__ rb) {
    int t = blockIdx.x;
    const float* xr = x + (size_t)t * HDIM;
    float* xo = g_xr + (size_t)t * HDIM;

    float acc[NEXP];
#pragma unroll
    for (int e = 0; e < NEXP; e++) acc[e] = 0.f;

    for (int h = threadIdx.x; h < HDIM; h += blockDim.x) {
        float xv = xr[h];
        xo[h] = tf32r(xv);
        const float* r = rw + (size_t)h * NEXP;
#pragma unroll
        for (int e = 0; e < NEXP; e++) acc[e] += xv * r[e];
    }

    __shared__ float red[256][NEXP + 1];
#pragma unroll
    for (int e = 0; e < NEXP; e++) red[threadIdx.x][e] = acc[e];
    __syncthreads();
    for (int s = 128; s > 0; s >>= 1) {
        if (threadIdx.x < s) {
#pragma unroll
            for (int e = 0; e < NEXP; e++)
                red[threadIdx.x][e] += red[threadIdx.x + s][e];
        }
        __syncthreads();
    }

    if (threadIdx.x == 0) {
        float lg[NEXP];
        float mx = -1e30f;
#pragma unroll
        for (int e = 0; e < NEXP; e++) {
            lg[e] = red[0][e] + rb[e];
            mx = fmaxf(mx, lg[e]);
        }
#pragma unroll
        for (int e = 0; e < NEXP; e++) lg[e] = expf(lg[e] - mx);

        int i0 = 0;
#pragma unroll
        for (int e = 1; e < NEXP; e++) if (lg[e] > lg[i0]) i0 = e;
        int i1 = (i0 == 0) ? 1 : 0;
#pragma unroll
        for (int e = 0; e < NEXP; e++) if (e != i0 && lg[e] > lg[i1]) i1 = e;

        float p0 = lg[i0], p1 = lg[i1];
        float inv = 1.f / (p0 + p1);

        int pos0 = atomicAdd(&g_cnt[i0], 1);
        g_tok[i0 * T_TOK + pos0]  = t * 2 + 0;
        g_gate[i0 * T_TOK + pos0] = p0 * inv;
        int pos1 = atomicAdd(&g_cnt[i1], 1);
        g_tok[i1 * T_TOK + pos1]  = t * 2 + 1;
        g_gate[i1 * T_TOK + pos1] = p1 * inv;
    }
}

// Grouped expert GEMM (tf32 tensor, cp.async 4-stage, 4 warps x 64x64):
// g_c[tok] += gelu(x[tok] @ W_e + b_e) * gate     (atomicAdd; exactly 2 adds
// per element onto zeroed buffer -> bitwise deterministic, fp add commutes)
__global__ __launch_bounds__(128, 2)
void expert_gemm_tf32(const float* __restrict__ eb) {
    extern __shared__ char smem[];
    unsigned sbase;
    asm("{ .reg .u64 t; cvta.to.shared.u64 t, %1; cvt.u32.u64 %0, t; }"
        : "=r"(sbase) : "l"(smem));

    int e = blockIdx.z;
    int cnt = g_cnt[e];
    int m0 = blockIdx.y * BM;
    if (m0 >= cnt) return;
    int n0 = blockIdx.x * BN;
    const float* w = g_ewr + (size_t)e * HDIM * DDIM;

    int tid = threadIdx.x;
    int lane = tid & 31;
    int wid  = tid >> 5;
    int wm = wid >> 1, wn = wid & 1;    // 2x2 warp grid, 64x64 each
    int lq = lane >> 2, tg = lane & 3;

    // A copy map: thread = one row (4 x cp16 covers 16 floats)
    int mA = tid;
    const float* asrc;
    int asz;
    {
        int gm = m0 + mA;
        if (gm < cnt) {
            asrc = g_xr + (size_t)(g_tok[e * T_TOK + gm] >> 1) * HDIM;
            asz = 16;
        } else { asrc = g_xr; asz = 0; }
    }
    unsigned adst = sbase + (mA * ASTR) * 4;
    // B copy map: 8 threads/k-row, 16 consecutive floats each (4 x cp16)
    int kB = tid >> 3;
    int nB = (tid & 7) * 16;
    const float* bsrc = w + (size_t)kB * DDIM + n0 + nB;
    unsigned bdst = sbase + NSTAGE * A_STAGE_BYTES + (kB * BSTR + nB) * 4;

#define ISSUE(st, k0)                                                               \
    do {                                                                            \
        _Pragma("unroll")                                                           \
        for (int cc = 0; cc < 4; cc++) {                                            \
            cp16(adst + (st) * A_STAGE_BYTES + cc * 16, asrc + (k0) + cc * 4, asz); \
            cp16(bdst + (st) * B_STAGE_BYTES + cc * 16,                             \
                 bsrc + (size_t)(k0) * DDIM + cc * 4, 16);                          \
        }                                                                           \
        cp_commit();                                                                \
    } while (0)

    float c[4][8][4];
#pragma unroll
    for (int i = 0; i < 4; i++)
#pragma unroll
        for (int j = 0; j < 8; j++)
#pragma unroll
            for (int q = 0; q < 4; q++) c[i][j][q] = 0.f;

    ISSUE(0, 0); ISSUE(1, BK); ISSUE(2, 2 * BK);

    const int NK = HDIM / BK;
#pragma unroll 1
    for (int i = 0; i < NK; i++) {
        cp_wait2();
        __syncthreads();
        int st = i & 3;
        compute_stage(
            (const unsigned (*)[ASTR])(smem + st * A_STAGE_BYTES),
            (const unsigned (*)[BSTR])(smem + NSTAGE * A_STAGE_BYTES + st * B_STAGE_BYTES),
            c, wm, wn, lq, tg);
        int nx = i + NSTAGE - 1;
        if (nx < NK) { ISSUE(nx & 3, nx * BK); }
        else         { cp_commit(); }
    }
#undef ISSUE

    // epilogue: bias + gelu + gate, atomicAdd into g_c[token]
    const float* be = eb + (size_t)e * DDIM;
#pragma unroll
    for (int mt = 0; mt < 4; mt++) {
        int rlo = wm * 64 + mt * 16 + lq;
        int rhi = rlo + 8;
        int glo = m0 + rlo, ghi = m0 + rhi;
        bool oklo = glo < cnt, okhi = ghi < cnt;
        int tklo = 0, tkhi = 0;
        float gtlo = 0.f, gthi = 0.f;
        if (oklo) { tklo = g_tok[e * T_TOK + glo] >> 1; gtlo = g_gate[e * T_TOK + glo]; }
        if (okhi) { tkhi = g_tok[e * T_TOK + ghi] >> 1; gthi = g_gate[e * T_TOK + ghi]; }
#pragma unroll
        for (int nt = 0; nt < 8; nt++) {
            int col = n0 + wn * 64 + nt * 8 + 2 * tg;
            float b0 = be[col], b1 = be[col + 1];
            if (oklo) {
                atomicAdd(g_c + (size_t)tklo * DDIM + col,     gelu_tanh(c[mt][nt][0] + b0) * gtlo);
                atomicAdd(g_c + (size_t)tklo * DDIM + col + 1, gelu_tanh(c[mt][nt][1] + b1) * gtlo);
            }
            if (okhi) {
                atomicAdd(g_c + (size_t)tkhi * DDIM + col,     gelu_tanh(c[mt][nt][2] + b0) * gthi);
                atomicAdd(g_c + (size_t)tkhi * DDIM + col + 1, gelu_tanh(c[mt][nt][3] + b1) * gthi);
            }
        }
    }
}

// Output projection (tf32 tensor, cp.async 4-stage, 4 warps x 64x64):
// out = g_c @ out_w + out_b   (g_c pre-rounded in place, out_w pre-rounded)
__global__ __launch_bounds__(128, 2)
void out_gemm_tf32(const float* __restrict__ ob, float* __restrict__ out) {
    extern __shared__ char smem[];
    unsigned sbase;
    asm("{ .reg .u64 t; cvta.to.shared.u64 t, %1; cvt.u32.u64 %0, t; }"
        : "=r"(sbase) : "l"(smem));

    int m0 = blockIdx.y * BM;
    int n0 = blockIdx.x * BN;

    int tid = threadIdx.x;
    int lane = tid & 31;
    int wid  = tid >> 5;
    int wm = wid >> 1, wn = wid & 1;
    int lq = lane >> 2, tg = lane & 3;

    int mA = tid;
    const float* asrc = g_c + (size_t)(m0 + mA) * DDIM;
    unsigned adst = sbase + (mA * ASTR) * 4;

    int kB = tid >> 3;
    int nB = (tid & 7) * 16;
    const float* bsrc = g_owr + (size_t)kB * DDIM + n0 + nB;
    unsigned bdst = sbase + NSTAGE * A_STAGE_BYTES + (kB * BSTR + nB) * 4;

#define ISSUE(st, k0)                                                               \
    do {                                                                            \
        _Pragma("unroll")                                                           \
        for (int cc = 0; cc < 4; cc++) {                                            \
            cp16(adst + (st) * A_STAGE_BYTES + cc * 16, asrc + (k0) + cc * 4, 16);  \
            cp16(bdst + (st) * B_STAGE_BYTES + cc * 16,                             \
                 bsrc + (size_t)(k0) * DDIM + cc * 4, 16);                          \
        }                                                                           \
        cp_commit();                                                                \
    } while (0)

    float c[4][8][4];
#pragma unroll
    for (int i = 0; i < 4; i++)
#pragma unroll
        for (int j = 0; j < 8; j++)
#pragma unroll
            for (int q = 0; q < 4; q++) c[i][j][q] = 0.f;

    ISSUE(0, 0); ISSUE(1, BK); ISSUE(2, 2 * BK);

    const int NK = DDIM / BK;
#pragma unroll 1
    for (int i = 0; i < NK; i++) {
        cp_wait2();
        __syncthreads();
        int st = i & 3;
        compute_stage(
            (const unsigned (*)[ASTR])(smem + st * A_STAGE_BYTES),
            (const unsigned (*)[BSTR])(smem + NSTAGE * A_STAGE_BYTES + st * B_STAGE_BYTES),
            c, wm, wn, lq, tg);
        int nx = i + NSTAGE - 1;
        if (nx < NK) { ISSUE(nx & 3, nx * BK); }
        else         { cp_commit(); }
    }
#undef ISSUE

#pragma unroll
    for (int mt = 0; mt < 4; mt++) {
        int rlo = m0 + wm * 64 + mt * 16 + lq;
        int rhi = rlo + 8;
#pragma unroll
        for (int nt = 0; nt < 8; nt++) {
            int col = n0 + wn * 64 + nt * 8 + 2 * tg;
            float b0 = ob[col], b1 = ob[col + 1];
            float2 o;
            o.x = c[mt][nt][0] + b0;
            o.y = c[mt][nt][1] + b1;
            *(float2*)(out + (size_t)rlo * DDIM + col) = o;
            o.x = c[mt][nt][2] + b0;
            o.y = c[mt][nt][3] + b1;
            *(float2*)(out + (size_t)rhi * DDIM + col) = o;
        }
    }
}

extern "C" void kernel_launch(void* const* d_in, const int* in_sizes, int n_in,
                              void* d_out, int out_size) {
    const float* x  = (const float*)d_in[0];
    const float* rw = (const float*)d_in[1];
    const float* rb = (const float*)d_in[2];
    const float* ew = (const float*)d_in[3];
    const float* eb = (const float*)d_in[4];
    const float* ow = (const float*)d_in[5];
    const float* ob = (const float*)d_in[6];
    float* out = (float*)d_out;

    cudaFuncSetAttribute(expert_gemm_tf32,
                         cudaFuncAttributeMaxDynamicSharedMemorySize, SMEM_BYTES);
    cudaFuncSetAttribute(out_gemm_tf32,
                         cudaFuncAttributeMaxDynamicSharedMemorySize, SMEM_BYTES);

    float* ewr; cudaGetSymbolAddress((void**)&ewr, g_ewr);
    float* owr; cudaGetSymbolAddress((void**)&owr, g_owr);

    zero_kernel<<<1024, 256>>>();
    router_kernel<<<T_TOK, 256>>>(x, rw, rb);

    preround_kernel<<<2048, 256>>>(ew, ewr, NEXP * HDIM * DDIM / 4);
    preround_kernel<<<1024, 256>>>(ow, owr, DDIM * DDIM / 4);

    dim3 g1(DDIM / BN, T_TOK / BM, NEXP);
    expert_gemm_tf32<<<g1, 128, SMEM_BYTES>>>(eb);

    round_gc_kernel<<<1024, 256>>>();

    dim3 g2(DDIM / BN, T_TOK / BM);
    out_gemm_tf32<<<g2, 128, SMEM_BYTES>>>(ob, out);
}

// round 17
// speedup vs baseline: 1.9799x; 1.9799x over previous
#include <cuda_runtime.h>
#include <cuda_fp16.h>
#include <math.h>

#define T_TOK 4096   // B*S
#define HDIM  2048
#define NEXP  8
#define DDIM  2048

#define BM 128
#define BN 128
#define BKH 32      // K per stage in halves (64B per row)
#define RSTR 20     // row stride in uint32 (16 data + 4 pad) -> conflict-free
#define NSTAGE 4

#define A_STAGE_BYTES (BM * RSTR * 4)      // 10240
#define B_STAGE_BYTES (BN * RSTR * 4)      // 10240 (B stored transposed: n rows, k contiguous)
#define STAGE_BYTES (A_STAGE_BYTES + B_STAGE_BYTES)
#define SMEM_BYTES (NSTAGE * STAGE_BYTES)  // 81920

// ---- scratch (static device globals: no runtime allocation) ----
__device__ int    g_cnt[NEXP];
__device__ int    g_tok[NEXP * T_TOK];    // token*2 + slot
__device__ float  g_gate[NEXP * T_TOK];
__device__ float  g_c[(size_t)T_TOK * DDIM];           // combined expert out (atomicAdd)
__device__ __half g_xh[(size_t)T_TOK * HDIM];          // fp16 x
__device__ __half g_ch[(size_t)T_TOK * DDIM];          // fp16 combined (A of out gemm)
__device__ __half g_ewh[(size_t)NEXP * HDIM * DDIM];   // fp16 expert_w TRANSPOSED [e][d][h]
__device__ __half g_owh[(size_t)DDIM * DDIM];          // fp16 out_w TRANSPOSED [f][d]

__device__ __forceinline__ float gelu_tanh(float v) {
    float v3 = v * v * v;
    return 0.5f * v * (1.0f + tanhf(0.7978845608028654f * (v + 0.044715f * v3)));
}

__device__ __forceinline__ void mma_f16(float* c, const unsigned* a, const unsigned* b) {
    asm volatile(
        "mma.sync.aligned.m16n8k16.row.col.f32.f16.f16.f32 "
        "{%0,%1,%2,%3}, {%4,%5,%6,%7}, {%8,%9}, {%0,%1,%2,%3};"
        : "+f"(c[0]), "+f"(c[1]), "+f"(c[2]), "+f"(c[3])
        : "r"(a[0]), "r"(a[1]), "r"(a[2]), "r"(a[3]), "r"(b[0]), "r"(b[1]));
}

__device__ __forceinline__ void cp16(unsigned dst, const void* src, int sz) {
    asm volatile("cp.async.cg.shared.global [%0], [%1], 16, %2;\n"
                 :: "r"(dst), "l"(src), "r"(sz));
}
__device__ __forceinline__ void cp_commit() {
    asm volatile("cp.async.commit_group;\n" ::: "memory");
}
__device__ __forceinline__ void cp_wait2() {
    asm volatile("cp.async.wait_group 2;\n" ::: "memory");
}

// One BK=32-half stage = two k16 chunks. 8 warps, each 64x32.
// As: [128 m-rows][16 uint32 k-pairs (+4 pad)]; Bs: [128 n-rows][same] (transposed B).
__device__ __forceinline__ void compute_stage(
    const unsigned (*__restrict__ As)[RSTR],
    const unsigned (*__restrict__ Bs)[RSTR],
    float c[4][4][4], int wm, int wn, int lq, int tg)
{
#pragma unroll
    for (int kc = 0; kc < 16; kc += 8) {   // uint32 offset of k16 chunk
        unsigned af[4][4];
        unsigned bf[4][2];
#pragma unroll
        for (int mt = 0; mt < 4; mt++) {
            int r = wm * 64 + mt * 16 + lq;
            af[mt][0] = As[r][kc + tg];
            af[mt][1] = As[r + 8][kc + tg];
            af[mt][2] = As[r][kc + tg + 4];
            af[mt][3] = As[r + 8][kc + tg + 4];
        }
#pragma unroll
        for (int nt = 0; nt < 4; nt++) {
            int nn = wn * 32 + nt * 8 + lq;
            bf[nt][0] = Bs[nn][kc + tg];
            bf[nt][1] = Bs[nn][kc + tg + 4];
        }
#pragma unroll
        for (int mt = 0; mt < 4; mt++)
#pragma unroll
            for (int nt = 0; nt < 4; nt++)
                mma_f16(c[mt][nt], af[mt], bf[nt]);
    }
}

// Zero g_cnt and g_c (float4 grid-stride)
__global__ void zero_kernel() {
    if (blockIdx.x == 0 && threadIdx.x < NEXP) g_cnt[threadIdx.x] = 0;
    int i = blockIdx.x * blockDim.x + threadIdx.x;
    const int n4 = T_TOK * DDIM / 4;
    float4 z = make_float4(0.f, 0.f, 0.f, 0.f);
    for (; i < n4; i += gridDim.x * blockDim.x)
        ((float4*)g_c)[i] = z;
}

// Convert + transpose: src [R][C] fp32 row-major -> dst [C][R] fp16 row-major
__global__ void cvt_t_kernel(const float* __restrict__ src, __half* __restrict__ dst,
                             int R, int C) {
    __shared__ float t[32][33];
    size_t zo = (size_t)blockIdx.z * (size_t)R * C;
    int r0 = blockIdx.y * 32, c0 = blockIdx.x * 32;
    int tx = threadIdx.x, ty = threadIdx.y;   // (32, 8)
#pragma unroll
    for (int i = 0; i < 4; i++)
        t[ty + 8 * i][tx] = src[zo + (size_t)(r0 + ty + 8 * i) * C + c0 + tx];
    __syncthreads();
#pragma unroll
    for (int i = 0; i < 4; i++)
        dst[zo + (size_t)(c0 + ty + 8 * i) * R + r0 + tx] =
            __float2half_rn(t[tx][ty + 8 * i]);
}

// g_c (fp32 sums) -> g_ch (fp16): one rounding AFTER the two-expert sum
__global__ void cvt_gc_kernel() {
    int i = blockIdx.x * blockDim.x + threadIdx.x;
    const int n4 = T_TOK * DDIM / 4;
    for (; i < n4; i += gridDim.x * blockDim.x) {
        float4 v = ((const float4*)g_c)[i];
        __half2 h0 = __floats2half2_rn(v.x, v.y);
        __half2 h1 = __floats2half2_rn(v.z, v.w);
        uint2 o;
        o.x = *(unsigned*)&h0;
        o.y = *(unsigned*)&h1;
        ((uint2*)g_ch)[i] = o;
    }
}

// One block per token: logits -> softmax -> top2 -> renorm -> append to lists.
// Also writes g_xh = fp16 x (fused: x is already being read).
__global__ void router_kernel(const float* __restrict__ x,
                              const float* __restrict__ rw,
                              const float* __restrict__ rb) {
    int t = blockIdx.x;
    const float* xr = x + (size_t)t * HDIM;
    __half* xo = g_xh + (size_t)t * HDIM;

    float acc[NEXP];
#pragma unroll
    for (int e = 0; e < NEXP; e++) acc[e] = 0.f;

    for (int h = threadIdx.x; h < HDIM; h += blockDim.x) {
        float xv = xr[h];
        xo[h] = __float2half_rn(xv);
        const float* r = rw + (size_t)h * NEXP;
#pragma unroll
        for (int e = 0; e < NEXP; e++) acc[e] += xv * r[e];
    }

    __shared__ float red[256][NEXP + 1];
#pragma unroll
    for (int e = 0; e < NEXP; e++) red[threadIdx.x][e] = acc[e];
    __syncthreads();
    for (int s = 128; s > 0; s >>= 1) {
        if (threadIdx.x < s) {
#pragma unroll
            for (int e = 0; e < NEXP; e++)
                red[threadIdx.x][e] += red[threadIdx.x + s][e];
        }
        __syncthreads();
    }

    if (threadIdx.x == 0) {
        float lg[NEXP];
        float mx = -1e30f;
#pragma unroll
        for (int e = 0; e < NEXP; e++) {
            lg[e] = red[0][e] + rb[e];
            mx = fmaxf(mx, lg[e]);
        }
#pragma unroll
        for (int e = 0; e < NEXP; e++) lg[e] = expf(lg[e] - mx);

        int i0 = 0;
#pragma unroll
        for (int e = 1; e < NEXP; e++) if (lg[e] > lg[i0]) i0 = e;
        int i1 = (i0 == 0) ? 1 : 0;
#pragma unroll
        for (int e = 0; e < NEXP; e++) if (e != i0 && lg[e] > lg[i1]) i1 = e;

        float p0 = lg[i0], p1 = lg[i1];
        float inv = 1.f / (p0 + p1);

        int pos0 = atomicAdd(&g_cnt[i0], 1);
        g_tok[i0 * T_TOK + pos0]  = t * 2 + 0;
        g_gate[i0 * T_TOK + pos0] = p0 * inv;
        int pos1 = atomicAdd(&g_cnt[i1], 1);
        g_tok[i1 * T_TOK + pos1]  = t * 2 + 1;
        g_gate[i1 * T_TOK + pos1] = p1 * inv;
    }
}

// Grouped expert GEMM (fp16 mma, fp32 acc, cp.async 4-stage, 8 warps x 64x32):
// g_c[tok] += gelu(x[tok] @ W_e + b_e) * gate   (atomicAdd; exactly 2 adds per
// element onto zeroed buffer -> bitwise deterministic, fp add commutes)
__global__ __launch_bounds__(256, 2)
void expert_gemm_f16(const float* __restrict__ eb) {
    extern __shared__ char smem[];
    unsigned sbase;
    asm("{ .reg .u64 t; cvta.to.shared.u64 t, %1; cvt.u32.u64 %0, t; }"
        : "=r"(sbase) : "l"(smem));

    int e = blockIdx.z;
    int cnt = g_cnt[e];
    int m0 = blockIdx.y * BM;
    if (m0 >= cnt) return;
    int n0 = blockIdx.x * BN;
    const __half* w = g_ewh + (size_t)e * HDIM * DDIM;   // [d][h], k=h contiguous

    int tid = threadIdx.x;
    int lane = tid & 31;
    int wid  = tid >> 5;
    int wm = wid >> 2, wn = wid & 3;
    int lq = lane >> 2, tg = lane & 3;

    // copy maps: 2 threads per row; each thread 32B of the 64B row (2 x cp16)
    int mr = tid >> 1;
    int hoff = (tid & 1) * 16;   // halves
    const __half* asrc;
    int asz;
    {
        int gm = m0 + mr;
        if (gm < cnt) {
            asrc = g_xh + (size_t)(g_tok[e * T_TOK + gm] >> 1) * HDIM + hoff;
            asz = 16;
        } else { asrc = g_xh; asz = 0; }
    }
    const __half* bsrc = w + (size_t)(n0 + mr) * HDIM + hoff;
    unsigned adst = sbase + mr * (RSTR * 4) + (tid & 1) * 32;
    unsigned bdst = adst + A_STAGE_BYTES;

#define ISSUE(st, k0)                                                  \
    do {                                                               \
        cp16(adst + (st) * STAGE_BYTES,      asrc + (k0),      asz);   \
        cp16(adst + (st) * STAGE_BYTES + 16, asrc + (k0) + 8,  asz);   \
        cp16(bdst + (st) * STAGE_BYTES,      bsrc + (k0),      16);    \
        cp16(bdst + (st) * STAGE_BYTES + 16, bsrc + (k0) + 8,  16);    \
        cp_commit();                                                   \
    } while (0)

    float c[4][4][4];
#pragma unroll
    for (int i = 0; i < 4; i++)
#pragma unroll
        for (int j = 0; j < 4; j++)
#pragma unroll
            for (int q = 0; q < 4; q++) c[i][j][q] = 0.f;

    ISSUE(0, 0); ISSUE(1, BKH); ISSUE(2, 2 * BKH);

    const int NK = HDIM / BKH;   // 64
#pragma unroll 1
    for (int i = 0; i < NK; i++) {
        cp_wait2();
        __syncthreads();
        int st = i & 3;
        compute_stage(
            (const unsigned (*)[RSTR])(smem + st * STAGE_BYTES),
            (const unsigned (*)[RSTR])(smem + st * STAGE_BYTES + A_STAGE_BYTES),
            c, wm, wn, lq, tg);
        int nx = i + NSTAGE - 1;
        if (nx < NK) { ISSUE(nx & 3, nx * BKH); }
        else         { cp_commit(); }
    }
#undef ISSUE

    // epilogue: bias + gelu + gate, atomicAdd into g_c[token]
    const float* be = eb + (size_t)e * DDIM;
#pragma unroll
    for (int mt = 0; mt < 4; mt++) {
        int rlo = wm * 64 + mt * 16 + lq;
        int rhi = rlo + 8;
        int glo = m0 + rlo, ghi = m0 + rhi;
        bool oklo = glo < cnt, okhi = ghi < cnt;
        int tklo = 0, tkhi = 0;
        float gtlo = 0.f, gthi = 0.f;
        if (oklo) { tklo = g_tok[e * T_TOK + glo] >> 1; gtlo = g_gate[e * T_TOK + glo]; }
        if (okhi) { tkhi = g_tok[e * T_TOK + ghi] >> 1; gthi = g_gate[e * T_TOK + ghi]; }
#pragma unroll
        for (int nt = 0; nt < 4; nt++) {
            int col = n0 + wn * 32 + nt * 8 + 2 * tg;
            float b0 = be[col], b1 = be[col + 1];
            if (oklo) {
                atomicAdd(g_c + (size_t)tklo * DDIM + col,     gelu_tanh(c[mt][nt][0] + b0) * gtlo);
                atomicAdd(g_c + (size_t)tklo * DDIM + col + 1, gelu_tanh(c[mt][nt][1] + b1) * gtlo);
            }
            if (okhi) {
                atomicAdd(g_c + (size_t)tkhi * DDIM + col,     gelu_tanh(c[mt][nt][2] + b0) * gthi);
                atomicAdd(g_c + (size_t)tkhi * DDIM + col + 1, gelu_tanh(c[mt][nt][3] + b1) * gthi);
            }
        }
    }
}

// Output projection (fp16 mma, fp32 acc): out = g_ch @ out_w + out_b
__global__ __launch_bounds__(256, 2)
void out_gemm_f16(const float* __restrict__ ob, float* __restrict__ out) {
    extern __shared__ char smem[];
    unsigned sbase;
    asm("{ .reg .u64 t; cvta.to.shared.u64 t, %1; cvt.u32.u64 %0, t; }"
        : "=r"(sbase) : "l"(smem));

    int m0 = blockIdx.y * BM;
    int n0 = blockIdx.x * BN;

    int tid = threadIdx.x;
    int lane = tid & 31;
    int wid  = tid >> 5;
    int wm = wid >> 2, wn = wid & 3;
    int lq = lane >> 2, tg = lane & 3;

    int mr = tid >> 1;
    int hoff = (tid & 1) * 16;
    const __half* asrc = g_ch + (size_t)(m0 + mr) * DDIM + hoff;
    const __half* bsrc = g_owh + (size_t)(n0 + mr) * DDIM + hoff;  // [f][d]
    unsigned adst = sbase + mr * (RSTR * 4) + (tid & 1) * 32;
    unsigned bdst = adst + A_STAGE_BYTES;

#define ISSUE(st, k0)                                                  \
    do {                                                               \
        cp16(adst + (st) * STAGE_BYTES,      asrc + (k0),      16);    \
        cp16(adst + (st) * STAGE_BYTES + 16, asrc + (k0) + 8,  16);    \
        cp16(bdst + (st) * STAGE_BYTES,      bsrc + (k0),      16);    \
        cp16(bdst + (st) * STAGE_BYTES + 16, bsrc + (k0) + 8,  16);    \
        cp_commit();                                                   \
    } while (0)

    float c[4][4][4];
#pragma unroll
    for (int i = 0; i < 4; i++)
#pragma unroll
        for (int j = 0; j < 4; j++)
#pragma unroll
            for (int q = 0; q < 4; q++) c[i][j][q] = 0.f;

    ISSUE(0, 0); ISSUE(1, BKH); ISSUE(2, 2 * BKH);

    const int NK = DDIM / BKH;
#pragma unroll 1
    for (int i = 0; i < NK; i++) {
        cp_wait2();
        __syncthreads();
        int st = i & 3;
        compute_stage(
            (const unsigned (*)[RSTR])(smem + st * STAGE_BYTES),
            (const unsigned (*)[RSTR])(smem + st * STAGE_BYTES + A_STAGE_BYTES),
            c, wm, wn, lq, tg);
        int nx = i + NSTAGE - 1;
        if (nx < NK) { ISSUE(nx & 3, nx * BKH); }
        else         { cp_commit(); }
    }
#undef ISSUE

#pragma unroll
    for (int mt = 0; mt < 4; mt++) {
        int rlo = m0 + wm * 64 + mt * 16 + lq;
        int rhi = rlo + 8;
#pragma unroll
        for (int nt = 0; nt < 4; nt++) {
            int col = n0 + wn * 32 + nt * 8 + 2 * tg;
            float b0 = ob[col], b1 = ob[col + 1];
            float2 o;
            o.x = c[mt][nt][0] + b0;
            o.y = c[mt][nt][1] + b1;
            *(float2*)(out + (size_t)rlo * DDIM + col) = o;
            o.x = c[mt][nt][2] + b0;
            o.y = c[mt][nt][3] + b1;
            *(float2*)(out + (size_t)rhi * DDIM + col) = o;
        }
    }
}

extern "C" void kernel_launch(void* const* d_in, const int* in_sizes, int n_in,
                              void* d_out, int out_size) {
    const float* x  = (const float*)d_in[0];
    const float* rw = (const float*)d_in[1];
    const float* rb = (const float*)d_in[2];
    const float* ew = (const float*)d_in[3];
    const float* eb = (const float*)d_in[4];
    const float* ow = (const float*)d_in[5];
    const float* ob = (const float*)d_in[6];
    float* out = (float*)d_out;

    cudaFuncSetAttribute(expert_gemm_f16,
                         cudaFuncAttributeMaxDynamicSharedMemorySize, SMEM_BYTES);
    cudaFuncSetAttribute(out_gemm_f16,
                         cudaFuncAttributeMaxDynamicSharedMemorySize, SMEM_BYTES);

    __half* ewh; cudaGetSymbolAddress((void**)&ewh, g_ewh);
    __half* owh; cudaGetSymbolAddress((void**)&owh, g_owh);

    zero_kernel<<<1024, 256>>>();
    router_kernel<<<T_TOK, 256>>>(x, rw, rb);

    // convert + transpose weights: ew [e][h][d] -> [e][d][h], ow [d][f] -> [f][d]
    cvt_t_kernel<<<dim3(DDIM / 32, HDIM / 32, NEXP), dim3(32, 8)>>>(ew, ewh, HDIM, DDIM);
    cvt_t_kernel<<<dim3(DDIM / 32, DDIM / 32, 1),    dim3(32, 8)>>>(ow, owh, DDIM, DDIM);

    dim3 g1(DDIM / BN, T_TOK / BM, NEXP);
    expert_gemm_f16<<<g1, 256, SMEM_BYTES>>>(eb);

    cvt_gc_kernel<<<1024, 256>>>();

    dim3 g2(DDIM / BN, T_TOK / BM);
    out_gemm_f16<<<g2, 256, SMEM_BYTES>>>(ob, out);
}